// round 4
// baseline (speedup 1.0000x reference)
#include <cuda_runtime.h>

#define H 128
#define NCOLP 131072
#define NICP  2000
#define NBCP  2000
#define NTOT  (NCOLP + NICP + 2*NBCP)

#define NWARP 8
#define PPW   2                  // points per warp
#define NBLOCKS 148
#define TILEPTS (NBLOCKS * NWARP * PPW)

// ---- dynamic smem layout (floats) ----
// [0, 3*H*H)            : W1,W2,W3 plain row-major (read via jq-rotated broadcast)
// [3*H*H, +NWARP*1024)  : per-warp transposed h buffers, XOR-swizzled (128 j x 8 r)
// [.., +32)             : 16 doubles for block reduction
#define OFF_WT  0
#define OFF_HT  (3*H*H)
#define OFF_RED (OFF_HT + NWARP*1024)
#define SMEM_FLOATS (OFF_RED + 32)
#define SMEM_BYTES  (SMEM_FLOATS * 4)      // 229,504 B

__device__ double g_acc;

__device__ __forceinline__ unsigned long long ffma2(unsigned long long a,
                                                    unsigned long long b,
                                                    unsigned long long c) {
    unsigned long long r;
    asm("fma.rn.f32x2 %0, %1, %2, %3;" : "=l"(r) : "l"(a), "l"(b), "l"(c));
    return r;
}
__device__ __forceinline__ unsigned long long pack2(float lo, float hi) {
    unsigned long long r;
    asm("mov.b64 %0, {%1, %2};" : "=l"(r) : "f"(lo), "f"(hi));
    return r;
}
__device__ __forceinline__ void unpack2(unsigned long long a, float& lo, float& hi) {
    asm("mov.b64 {%0, %1}, %2;" : "=f"(lo), "=f"(hi) : "l"(a));
}

// XOR-swizzled byte offset of h^T[j][*] within a warp's 4KB buffer:
// float index = ((j*8) ^ ((j>>5)*8)) + r  ->  bytes = (j*32 ^ (j>>5)*32) + r*4
__device__ __forceinline__ int ht_off(int j) {
    return (j * 32) ^ ((j >> 5) * 32);
}

extern "C" __global__ void __launch_bounds__(256, 1)
pinn_kernel(const float* __restrict__ x_col, const float* __restrict__ t_col,
            const float* __restrict__ x_ic,  const float* __restrict__ t_ic,
            const float* __restrict__ x_bcl, const float* __restrict__ x_bcr,
            const float* __restrict__ t_bc,
            const float* __restrict__ W0, const float* __restrict__ b0,
            const float* __restrict__ W1, const float* __restrict__ b1,
            const float* __restrict__ W2, const float* __restrict__ b2,
            const float* __restrict__ W3, const float* __restrict__ b3,
            const float* __restrict__ W4, const float* __restrict__ b4,
            const float* __restrict__ pD, const float* __restrict__ pchi)
{
    extern __shared__ float smem[];
    const int tid  = threadIdx.x;
    const int lane = tid & 31;
    const int warp = tid >> 5;

    const int jq = lane >> 3;        // j-quarter 0..3
    const int r  = lane & 7;         // (p,v) row 0..7
    const int p  = r >> 2;           // point within warp 0..1
    const int v  = r & 3;            // Taylor stream 0..3

    // ---- stage hidden weights into smem (plain row-major) ----
    {
        const float* src[3] = {W1, W2, W3};
        for (int k = 0; k < 3; ++k) {
            float* dst = smem + OFF_WT + k * (H*H);
            for (int idx = tid; idx < H*H; idx += blockDim.x)
                dst[idx] = src[k][idx];
        }
    }
    __syncthreads();

    const float b4v  = __ldg(&b4[0]);
    const float Dv   = __ldg(&pD[0]);
    const float chiv = __ldg(&pchi[0]);

    char* hT = (char*)(smem + OFF_HT + warp * 1024);   // 4KB per warp

    // per-k weight read offsets (bytes): column j = jq*32 + rot, rot = (8jq+4k)&31.
    // jq-rotation makes the 4 quarters' 16B loads hit disjoint bank groups.
    int koff[8];
    #pragma unroll
    for (int k = 0; k < 8; ++k)
        koff[k] = jq * 32 * 4 + (((8 * jq + 4 * k) & 31) * 4);

    double local = 0.0;

    for (int base = (blockIdx.x * NWARP + warp) * PPW; base < NTOT; base += TILEPTS) {

        // ---- fetch this warp's 2 points ----
        float px[PPW], pt[PPW]; int ptype[PPW];
        #pragma unroll
        for (int q = 0; q < PPW; ++q) {
            int pid = base + q;
            float x = 0.f, t = 0.f; int ty = 3;
            if (pid < NCOLP)                    { x = x_col[pid];               t = t_col[pid];             ty = 0; }
            else if (pid < NCOLP + NICP)        { int u_ = pid - NCOLP;         x = x_ic[u_];  t = t_ic[u_]; ty = 1; }
            else if (pid < NCOLP + NICP + NBCP) { int u_ = pid - NCOLP - NICP;  x = x_bcl[u_]; t = t_bc[u_]; ty = 2; }
            else if (pid < NTOT)                { int u_ = pid-NCOLP-NICP-NBCP; x = x_bcr[u_]; t = t_bc[u_]; ty = 2; }
            px[q] = x; pt[q] = t; ptype[q] = ty;
        }
        const float myx = px[p], myt = pt[p];

        // ---- layer 0: write this lane's stream-v activation for 32 neurons ----
        #pragma unroll 4
        for (int jj = 0; jj < 32; ++jj) {
            int j = jq * 32 + jj;
            float w0x = __ldg(&W0[j]);
            float w0t = __ldg(&W0[H + j]);
            float z   = fmaf(myx, w0x, fmaf(myt, w0t, __ldg(&b0[j])));
            float e   = __expf(-z);
            float s   = __fdividef(1.f, 1.f + e);
            float s1s = s * (1.f - s);
            float f1  = fmaf(z, s1s, s);
            float val;
            if (v == 0)      val = z * s;
            else if (v == 1) val = f1 * w0x;
            else if (v == 2) val = f1 * w0t;
            else {
                float f2 = s1s * fmaf(z, fmaf(-2.f, s, 1.f), 2.f);
                val = f2 * w0x * w0x;            // zxx = 0 at layer 0
            }
            *(float*)(hT + ht_off(j) + r * 4) = val;
        }
        __syncwarp();

        // ---- 3 hidden layers ----
        float spart = 0.f;
        #pragma unroll 1
        for (int L = 0; L < 3; ++L) {
            const char* Wt = (const char*)(smem + OFF_WT + L * (H*H));
            const float* bL = (L == 0) ? b1 : (L == 1) ? b2 : b3;

            unsigned long long acc[16];
            #pragma unroll
            for (int m = 0; m < 16; ++m) acc[m] = 0ull;

            #pragma unroll 8
            for (int i = 0; i < H; ++i) {
                float hv = *(const float*)(hT + (((i*32) ^ ((i>>5)*32)) + r*4));
                unsigned long long h2 = pack2(hv, hv);
                const char* Wrow = Wt + i * (H * 4);
                #pragma unroll
                for (int k = 0; k < 8; ++k) {
                    ulonglong2 w2 = *(const ulonglong2*)(Wrow + koff[k]);
                    acc[2*k]   = ffma2(h2, w2.x, acc[2*k]);
                    acc[2*k+1] = ffma2(h2, w2.y, acc[2*k+1]);
                }
            }
            __syncwarp();   // all hT reads complete before overwrite

            const bool last = (L == 2);
            #pragma unroll
            for (int k = 0; k < 8; ++k) {
                int jb = jq * 32 + ((8 * jq + 4 * k) & 31);
                #pragma unroll
                for (int hh = 0; hh < 2; ++hh) {
                    float ze[2];
                    unpack2(acc[2*k + hh], ze[0], ze[1]);
                    #pragma unroll
                    for (int e = 0; e < 2; ++e) {
                        int j = jb + 2 * hh + e;
                        float zmine = ze[e];
                        if (v == 0) zmine += __ldg(&bL[j]);
                        float z0 = __shfl_sync(0xffffffffu, zmine, lane & ~3);
                        float zx = __shfl_sync(0xffffffffu, zmine, (lane & ~3) | 1);
                        float ex  = __expf(-z0);
                        float s   = __fdividef(1.f, 1.f + ex);
                        float s1s = s * (1.f - s);
                        float f1  = fmaf(z0, s1s, s);
                        float val;
                        if (v == 0)      val = z0 * s;
                        else if (v == 3) {
                            float f2 = s1s * fmaf(z0, fmaf(-2.f, s, 1.f), 2.f);
                            val = fmaf(f2 * zx, zx, f1 * zmine);
                        } else           val = f1 * zmine;
                        if (!last)
                            *(float*)(hT + ht_off(j) + r * 4) = val;
                        else
                            spart = fmaf(val, __ldg(&W4[j]), spart);
                    }
                }
            }
            if (!last) __syncwarp();
        }

        // ---- output layer: reduce over j-quarters, assemble per-point loss ----
        spart += __shfl_xor_sync(0xffffffffu, spart, 8);
        spart += __shfl_xor_sync(0xffffffffu, spart, 16);
        // lanes with same (p,v) now agree; gather the 4 streams of own point
        int pb = lane & 4;   // = p*4 for the r-part
        float u_  = __shfl_sync(0xffffffffu, spart, pb + 0) + b4v;
        float ux  = __shfl_sync(0xffffffffu, spart, pb + 1);
        float ut  = __shfl_sync(0xffffffffu, spart, pb + 2);
        float uxx = __shfl_sync(0xffffffffu, spart, pb + 3);

        if (lane == 0 || lane == 4) {
            int q = lane >> 2;
            float x = px[q];
            float contrib = 0.f;
            int ty = ptype[q];
            if (ty == 0) {
                float a   = x - 0.7f;
                float E   = __expf(-50.f * a * a);
                float dS  = -100.f * a * E;
                float dS2 = 100.f * E * fmaf(100.f * a, a, -1.f);
                float res = ut - Dv * uxx + chiv * (ux * dS + u_ * dS2);
                contrib = res * res * (1.f / NCOLP);
            } else if (ty == 1) {
                float d0  = x - 0.3f;
                float icv = 0.1f + 0.05f * __expf(-100.f * d0 * d0);
                float d   = u_ - icv;
                contrib = d * d * (1.f / NICP);
            } else if (ty == 2) {
                contrib = ux * ux * (1.f / NBCP);
            }
            local += (double)contrib;
        }
        __syncwarp();
    }

    // ---- block reduction ----
    {
        double o = 0.0;
        long long bits = __shfl_sync(0xffffffffu, __double_as_longlong(local), 4);
        if (lane == 0) o = local + __longlong_as_double(bits);
        double* red = (double*)(smem + OFF_RED);
        __syncthreads();
        if (lane == 0) red[warp] = o;
        __syncthreads();
        if (tid == 0) {
            double s = 0.0;
            #pragma unroll
            for (int w = 0; w < NWARP; ++w) s += red[w];
            atomicAdd(&g_acc, s);
        }
    }
}

__global__ void k_zero() { g_acc = 0.0; }
__global__ void k_final(float* out) { out[0] = (float)g_acc; }

extern "C" void kernel_launch(void* const* d_in, const int* in_sizes, int n_in,
                              void* d_out, int out_size) {
    (void)in_sizes; (void)n_in; (void)out_size;
    cudaFuncSetAttribute(pinn_kernel,
                         cudaFuncAttributeMaxDynamicSharedMemorySize, SMEM_BYTES);
    k_zero<<<1, 1>>>();
    pinn_kernel<<<NBLOCKS, 256, SMEM_BYTES>>>(
        (const float*)d_in[0],  (const float*)d_in[1],  (const float*)d_in[2],
        (const float*)d_in[3],  (const float*)d_in[4],  (const float*)d_in[5],
        (const float*)d_in[6],  (const float*)d_in[7],  (const float*)d_in[8],
        (const float*)d_in[9],  (const float*)d_in[10], (const float*)d_in[11],
        (const float*)d_in[12], (const float*)d_in[13], (const float*)d_in[14],
        (const float*)d_in[15], (const float*)d_in[16], (const float*)d_in[17],
        (const float*)d_in[18]);
    k_final<<<1, 1>>>((float*)d_out);
}

// round 5
// speedup vs baseline: 1.7736x; 1.7736x over previous
#include <cuda_runtime.h>

#define H 128
#define NCOLP 131072
#define NICP  2000
#define NBCP  2000
#define NTOT  (NCOLP + NICP + 2*NBCP)

#define NWARP 8
#define PPW   2
#define NBLOCKS 148
#define TILEPTS (NBLOCKS * NWARP * PPW)

// ---- dynamic smem layout (floats) ----
// [0, 3*H*H)        : W1,W2,W3 row-major (lane-strided float4 reads)
// [3*H*H, +8*1024)  : per-warp transpose buffers: 4 streams x 128 i x 2 pts
// [.., +64)         : block reduction
#define OFF_WT  0
#define OFF_HT  (3*H*H)
#define OFF_RED (OFF_HT + NWARP*1024)
#define SMEM_FLOATS (OFF_RED + 64)
#define SMEM_BYTES  (SMEM_FLOATS * 4)

__device__ double g_acc;

__device__ __forceinline__ unsigned long long ffma2(unsigned long long a,
                                                    unsigned long long b,
                                                    unsigned long long c) {
    unsigned long long r;
    asm("fma.rn.f32x2 %0, %1, %2, %3;" : "=l"(r) : "l"(a), "l"(b), "l"(c));
    return r;
}
__device__ __forceinline__ unsigned long long pack2(float lo, float hi) {
    unsigned long long r;
    asm("mov.b64 %0, {%1, %2};" : "=l"(r) : "f"(lo), "f"(hi));
    return r;
}
__device__ __forceinline__ void unpack2(unsigned long long a, float& lo, float& hi) {
    asm("mov.b64 {%0, %1}, %2;" : "=f"(lo), "=f"(hi) : "l"(a));
}

// SiLU value + derivative-stream propagation
__device__ __forceinline__ void act4(float z, float zx, float zt, float zxx,
                                     float& a, float& ax, float& at_, float& axx) {
    float e   = __expf(-z);
    float s   = __fdividef(1.f, 1.f + e);
    float s1s = s * (1.f - s);
    float f1  = fmaf(z, s1s, s);
    float f2  = s1s * fmaf(z, fmaf(-2.f, s, 1.f), 2.f);
    a   = z * s;
    ax  = f1 * zx;
    at_ = f1 * zt;
    axx = fmaf(f2 * zx, zx, f1 * zxx);
}

extern "C" __global__ void __launch_bounds__(256, 1)
pinn_kernel(const float* __restrict__ x_col, const float* __restrict__ t_col,
            const float* __restrict__ x_ic,  const float* __restrict__ t_ic,
            const float* __restrict__ x_bcl, const float* __restrict__ x_bcr,
            const float* __restrict__ t_bc,
            const float* __restrict__ W0, const float* __restrict__ b0,
            const float* __restrict__ W1, const float* __restrict__ b1,
            const float* __restrict__ W2, const float* __restrict__ b2,
            const float* __restrict__ W3, const float* __restrict__ b3,
            const float* __restrict__ W4, const float* __restrict__ b4,
            const float* __restrict__ pD, const float* __restrict__ pchi)
{
    extern __shared__ float smem[];
    const int tid  = threadIdx.x;
    const int lane = tid & 31;
    const int warp = tid >> 5;

    // ---- stage hidden weights into smem ----
    {
        const float* src[3] = {W1, W2, W3};
        for (int k = 0; k < 3; ++k) {
            float* dst = smem + OFF_WT + k * (H*H);
            for (int idx = tid; idx < H*H; idx += blockDim.x)
                dst[idx] = src[k][idx];
        }
    }
    __syncthreads();

    // ---- per-lane preloads: lane owns neurons j = 4*lane + jj ----
    float w0x[4], w0t[4], b0c[4], bc1[4], bc2[4], bc3[4], w4c[4];
    #pragma unroll
    for (int jj = 0; jj < 4; ++jj) {
        int j = 4 * lane + jj;
        w0x[jj] = __ldg(&W0[j]); w0t[jj] = __ldg(&W0[H + j]); b0c[jj] = __ldg(&b0[j]);
        bc1[jj] = __ldg(&b1[j]); bc2[jj] = __ldg(&b2[j]);     bc3[jj] = __ldg(&b3[j]);
        w4c[jj] = __ldg(&W4[j]);
    }
    const float b4v  = __ldg(&b4[0]);
    const float Dv   = __ldg(&pD[0]);
    const float chiv = __ldg(&pchi[0]);

    char* hT = (char*)(smem + OFF_HT + warp * 1024);   // 4KB: [v][i][p]

    double local = 0.0;

    for (int base = (blockIdx.x * NWARP + warp) * PPW; base < NTOT; base += TILEPTS) {

        // ---- fetch this warp's 2 points ----
        float px[2], pt[2]; int ptype[2];
        #pragma unroll
        for (int q = 0; q < 2; ++q) {
            int pid = base + q;
            float x = 0.f, t = 0.f; int ty = 3;
            if (pid < NCOLP)                    { x = x_col[pid];               t = t_col[pid];             ty = 0; }
            else if (pid < NCOLP + NICP)        { int u_ = pid - NCOLP;         x = x_ic[u_];  t = t_ic[u_]; ty = 1; }
            else if (pid < NCOLP + NICP + NBCP) { int u_ = pid - NCOLP - NICP;  x = x_bcl[u_]; t = t_bc[u_]; ty = 2; }
            else if (pid < NTOT)                { int u_ = pid-NCOLP-NICP-NBCP; x = x_bcr[u_]; t = t_bc[u_]; ty = 2; }
            px[q] = x; pt[q] = t; ptype[q] = ty;
        }

        // ---- layer 0: in-lane, 4 neurons x 2 points x 4 streams ----
        float out[4][2][4];   // [v][p][jj]
        #pragma unroll
        for (int jj = 0; jj < 4; ++jj)
            #pragma unroll
            for (int p = 0; p < 2; ++p) {
                float z = fmaf(px[p], w0x[jj], fmaf(pt[p], w0t[jj], b0c[jj]));
                act4(z, w0x[jj], w0t[jj], 0.f,
                     out[0][p][jj], out[1][p][jj], out[2][p][jj], out[3][p][jj]);
            }

        // ---- transpose via smem: [v][i][p] layout, then hreg[v][c] = (h_p0,h_p1) ----
        unsigned long long hreg[4][4];
        {
            #pragma unroll
            for (int v = 0; v < 4; ++v) {
                *(float4*)(hT + v*1024 + lane*32) =
                    make_float4(out[v][0][0], out[v][1][0], out[v][0][1], out[v][1][1]);
                *(float4*)(hT + v*1024 + lane*32 + 16) =
                    make_float4(out[v][0][2], out[v][1][2], out[v][0][3], out[v][1][3]);
            }
            __syncwarp();
            #pragma unroll
            for (int v = 0; v < 4; ++v)
                #pragma unroll
                for (int c = 0; c < 4; ++c)
                    hreg[v][c] = *(const unsigned long long*)(hT + v*1024 + (lane + 32*c)*8);
            __syncwarp();
        }

        // ---- 3 hidden layers ----
        float sp[2][4];       // output-layer partials [p][v]
        #pragma unroll
        for (int p = 0; p < 2; ++p)
            #pragma unroll
            for (int v = 0; v < 4; ++v) sp[p][v] = 0.f;

        #pragma unroll 1
        for (int L = 0; L < 3; ++L) {
            const char* Wt = (const char*)(smem + OFF_WT + L * (H*H));

            unsigned long long acc[4][4];   // [v][jj], each = (sum_p0, sum_p1)
            #pragma unroll
            for (int v = 0; v < 4; ++v)
                #pragma unroll
                for (int jj = 0; jj < 4; ++jj) acc[v][jj] = 0ull;

            #pragma unroll
            for (int c = 0; c < 4; ++c) {
                #pragma unroll 8
                for (int sl = 0; sl < 32; ++sl) {
                    const int i = c * 32 + sl;
                    const float4 wv = *(const float4*)(Wt + i*512 + lane*16);
                    unsigned long long w00 = pack2(wv.x, wv.x);
                    unsigned long long w11 = pack2(wv.y, wv.y);
                    unsigned long long w22 = pack2(wv.z, wv.z);
                    unsigned long long w33 = pack2(wv.w, wv.w);
                    #pragma unroll
                    for (int v = 0; v < 4; ++v) {
                        unsigned long long h2 = __shfl_sync(0xffffffffu, hreg[v][c], sl);
                        acc[v][0] = ffma2(h2, w00, acc[v][0]);
                        acc[v][1] = ffma2(h2, w11, acc[v][1]);
                        acc[v][2] = ffma2(h2, w22, acc[v][2]);
                        acc[v][3] = ffma2(h2, w33, acc[v][3]);
                    }
                }
            }

            const bool last = (L == 2);
            #pragma unroll
            for (int jj = 0; jj < 4; ++jj) {
                float z0[2], zx[2], zt[2], zxx[2];
                unpack2(acc[0][jj], z0[0],  z0[1]);
                unpack2(acc[1][jj], zx[0],  zx[1]);
                unpack2(acc[2][jj], zt[0],  zt[1]);
                unpack2(acc[3][jj], zxx[0], zxx[1]);
                float bb = (L == 0) ? bc1[jj] : ((L == 1) ? bc2[jj] : bc3[jj]);
                #pragma unroll
                for (int p = 0; p < 2; ++p) {
                    float a, ax, at_, axx;
                    act4(z0[p] + bb, zx[p], zt[p], zxx[p], a, ax, at_, axx);
                    if (!last) {
                        out[0][p][jj] = a;   out[1][p][jj] = ax;
                        out[2][p][jj] = at_; out[3][p][jj] = axx;
                    } else {
                        sp[p][0] = fmaf(a,   w4c[jj], sp[p][0]);
                        sp[p][1] = fmaf(ax,  w4c[jj], sp[p][1]);
                        sp[p][2] = fmaf(at_, w4c[jj], sp[p][2]);
                        sp[p][3] = fmaf(axx, w4c[jj], sp[p][3]);
                    }
                }
            }

            if (!last) {   // transpose for next layer
                #pragma unroll
                for (int v = 0; v < 4; ++v) {
                    *(float4*)(hT + v*1024 + lane*32) =
                        make_float4(out[v][0][0], out[v][1][0], out[v][0][1], out[v][1][1]);
                    *(float4*)(hT + v*1024 + lane*32 + 16) =
                        make_float4(out[v][0][2], out[v][1][2], out[v][0][3], out[v][1][3]);
                }
                __syncwarp();
                #pragma unroll
                for (int v = 0; v < 4; ++v)
                    #pragma unroll
                    for (int c = 0; c < 4; ++c)
                        hreg[v][c] = *(const unsigned long long*)(hT + v*1024 + (lane + 32*c)*8);
                __syncwarp();
            }
        }

        // ---- warp reduction of the 8 partials; lane 0 assembles loss ----
        #pragma unroll
        for (int off = 16; off; off >>= 1)
            #pragma unroll
            for (int p = 0; p < 2; ++p)
                #pragma unroll
                for (int v = 0; v < 4; ++v)
                    sp[p][v] += __shfl_xor_sync(0xffffffffu, sp[p][v], off);

        if (lane == 0) {
            #pragma unroll
            for (int p = 0; p < 2; ++p) {
                float u_  = sp[p][0] + b4v;
                float ux  = sp[p][1];
                float ut  = sp[p][2];
                float uxx = sp[p][3];
                float x   = px[p];
                float contrib = 0.f;
                int ty = ptype[p];
                if (ty == 0) {
                    float a   = x - 0.7f;
                    float E   = __expf(-50.f * a * a);
                    float dS  = -100.f * a * E;
                    float dS2 = 100.f * E * fmaf(100.f * a, a, -1.f);
                    float res = ut - Dv * uxx + chiv * (ux * dS + u_ * dS2);
                    contrib = res * res * (1.f / NCOLP);
                } else if (ty == 1) {
                    float d0  = x - 0.3f;
                    float icv = 0.1f + 0.05f * __expf(-100.f * d0 * d0);
                    float d   = u_ - icv;
                    contrib = d * d * (1.f / NICP);
                } else if (ty == 2) {
                    contrib = ux * ux * (1.f / NBCP);
                }
                local += (double)contrib;
            }
        }
    }

    // ---- block reduction ----
    {
        double* red = (double*)(smem + OFF_RED);
        __syncthreads();
        if (lane == 0) red[warp] = local;
        __syncthreads();
        if (tid == 0) {
            double s = 0.0;
            #pragma unroll
            for (int w = 0; w < NWARP; ++w) s += red[w];
            atomicAdd(&g_acc, s);
        }
    }
}

__global__ void k_zero() { g_acc = 0.0; }
__global__ void k_final(float* out) { out[0] = (float)g_acc; }

extern "C" void kernel_launch(void* const* d_in, const int* in_sizes, int n_in,
                              void* d_out, int out_size) {
    (void)in_sizes; (void)n_in; (void)out_size;
    cudaFuncSetAttribute(pinn_kernel,
                         cudaFuncAttributeMaxDynamicSharedMemorySize, SMEM_BYTES);
    k_zero<<<1, 1>>>();
    pinn_kernel<<<NBLOCKS, 256, SMEM_BYTES>>>(
        (const float*)d_in[0],  (const float*)d_in[1],  (const float*)d_in[2],
        (const float*)d_in[3],  (const float*)d_in[4],  (const float*)d_in[5],
        (const float*)d_in[6],  (const float*)d_in[7],  (const float*)d_in[8],
        (const float*)d_in[9],  (const float*)d_in[10], (const float*)d_in[11],
        (const float*)d_in[12], (const float*)d_in[13], (const float*)d_in[14],
        (const float*)d_in[15], (const float*)d_in[16], (const float*)d_in[17],
        (const float*)d_in[18]);
    k_final<<<1, 1>>>((float*)d_out);
}

// round 9
// speedup vs baseline: 1.9996x; 1.1274x over previous
#include <cuda_runtime.h>
#include <cuda_bf16.h>
#include <cstdint>

#define H 128
#define NCOLP 131072
#define NICP  2000
#define NBCP  2000
#define NTOT  (NCOLP + NICP + 2*NBCP)
#define NBLOCKS 148
#define NTHREADS 256
#define PTS_PER_WARP 4
#define PASS_STRIDE (NBLOCKS * 8 * PTS_PER_WARP)   // 4736 points per grid pass

// ---- smem byte offsets ----
// W blocks: for L in 0..2: Wh at L*65536, Wl at L*65536+32768 (each 32KB, [k][n] bf16,
// 256B rows, 16B-chunk XOR swizzle: chunk' = chunk ^ (k&7))
#define SM_W     0
#define SM_CONST 196608
// const floats: [0]=b1,[128]=b2,[256]=b3,[384]=w0x,[512]=w0t,[640]=b0,[768]=W4
#define SM_RED   (SM_CONST + 3584)
#define SMEM_BYTES (SM_RED + 128)

__device__ double g_acc;

__device__ __forceinline__ uint32_t smem_to_u32(const void* p) {
    uint32_t a;
    asm("{ .reg .u64 t; cvta.to.shared.u64 t, %1; cvt.u32.u64 %0, t; }"
        : "=r"(a) : "l"(p));
    return a;
}

__device__ __forceinline__ void mma_bf16(float* c, const unsigned* a,
                                         unsigned b0, unsigned b1) {
    asm volatile("mma.sync.aligned.m16n8k16.row.col.f32.bf16.bf16.f32 "
        "{%0,%1,%2,%3}, {%4,%5,%6,%7}, {%8,%9}, {%0,%1,%2,%3};"
        : "+f"(c[0]), "+f"(c[1]), "+f"(c[2]), "+f"(c[3])
        : "r"(a[0]), "r"(a[1]), "r"(a[2]), "r"(a[3]), "r"(b0), "r"(b1));
}
__device__ __forceinline__ void ldsm4t(unsigned* r, uint32_t addr) {
    asm volatile("ldmatrix.sync.aligned.m8n8.x4.trans.shared.b16 {%0,%1,%2,%3}, [%4];"
        : "=r"(r[0]), "=r"(r[1]), "=r"(r[2]), "=r"(r[3]) : "r"(addr));
}

// split val pairs into hi (bf16-rn) + lo (bf16-rn of exact residual)
__device__ __forceinline__ void repack8(const float* val, unsigned* aht, unsigned* alt) {
    #pragma unroll
    for (int q = 0; q < 4; ++q) {
        float v0 = val[2*q], v1 = val[2*q + 1];
        unsigned hp;
        asm("cvt.rn.bf16x2.f32 %0, %1, %2;" : "=r"(hp) : "f"(v1), "f"(v0));
        float h0 = __uint_as_float(hp << 16);           // low half -> f32
        float h1 = __uint_as_float(hp & 0xFFFF0000u);   // high half -> f32
        float l0 = v0 - h0, l1 = v1 - h1;
        unsigned lp;
        asm("cvt.rn.bf16x2.f32 %0, %1, %2;" : "=r"(lp) : "f"(l1), "f"(l0));
        aht[q] = hp; alt[q] = lp;
    }
}

// one GEMM layer: C[16 tiles][4] = (Ah+Al)*(Wh+Wl), 3 products
__device__ __forceinline__ void mma_layer(float (&C)[16][4],
                                          const unsigned (&ah)[8][4],
                                          const unsigned (&al)[8][4],
                                          uint32_t whB, uint32_t wlB, int lane) {
    #pragma unroll
    for (int nt = 0; nt < 16; ++nt)
        #pragma unroll
        for (int q = 0; q < 4; ++q) C[nt][q] = 0.f;
    const int g = lane >> 3, lr = lane & 7;
    const int krow = ((g & 1) << 3) + lr;    // row within ktile
    const int ccg  = g >> 1;                 // which n8-chunk of the pair
    #pragma unroll
    for (int np = 0; np < 8; ++np) {
        #pragma unroll
        for (int kt = 0; kt < 8; ++kt) {
            int k  = 16 * kt + krow;
            int cc = 2 * np + ccg;
            uint32_t off = (uint32_t)(k * 256 + ((cc ^ (k & 7)) << 4));
            unsigned bh[4], bl[4];
            ldsm4t(bh, whB + off);
            ldsm4t(bl, wlB + off);
            mma_bf16(C[2*np],   ah[kt], bh[0], bh[1]);
            mma_bf16(C[2*np],   al[kt], bh[0], bh[1]);
            mma_bf16(C[2*np],   ah[kt], bl[0], bl[1]);
            mma_bf16(C[2*np+1], ah[kt], bh[2], bh[3]);
            mma_bf16(C[2*np+1], al[kt], bh[2], bh[3]);
            mma_bf16(C[2*np+1], ah[kt], bl[2], bl[3]);
        }
    }
}

// SiLU-Taylor activation on 8 C-elements of one tile-pair.
// z[0..3] = C[2t], z[4..7] = C[2t+1]; n0 = 16t + 2*(lane&3).
__device__ __forceinline__ void act8(float* z, int v, int lane,
                                     const float* sbL, int n0, float* val) {
    if (v == 0) {   // bias only enters the value stream
        float2 ba = *(const float2*)&sbL[n0];
        float2 bb = *(const float2*)&sbL[n0 + 8];
        z[0] += ba.x; z[1] += ba.y; z[2] += ba.x; z[3] += ba.y;
        z[4] += bb.x; z[5] += bb.y; z[6] += bb.x; z[7] += bb.y;
    }
    const int zl = (lane & ~15) | (lane & 3);   // v=0 lane of this (point, col)
    #pragma unroll
    for (int i = 0; i < 8; ++i) {
        float zm = z[i];
        float z0 = __shfl_sync(0xffffffffu, zm, zl);
        float zx = __shfl_sync(0xffffffffu, zm, zl + 4);
        float e   = __expf(-z0);
        float s   = __fdividef(1.f, 1.f + e);
        float s1s = s * (1.f - s);
        float f1  = fmaf(z0, s1s, s);
        float f2  = s1s * fmaf(z0, fmaf(-2.f, s, 1.f), 2.f);
        float av  = z0 * s;                       // value stream
        float dv  = f1 * zm;                      // d/dx, d/dt streams
        float xv  = fmaf(f2 * zx, zx, f1 * zm);   // d2/dx2 stream
        val[i] = (v == 0) ? av : ((v == 3) ? xv : dv);
    }
}

extern "C" __global__ void __launch_bounds__(NTHREADS, 1)
pinn_kernel(const float* __restrict__ x_col, const float* __restrict__ t_col,
            const float* __restrict__ x_ic,  const float* __restrict__ t_ic,
            const float* __restrict__ x_bcl, const float* __restrict__ x_bcr,
            const float* __restrict__ t_bc,
            const float* __restrict__ W0, const float* __restrict__ b0,
            const float* __restrict__ W1, const float* __restrict__ b1,
            const float* __restrict__ W2, const float* __restrict__ b2,
            const float* __restrict__ W3, const float* __restrict__ b3,
            const float* __restrict__ W4, const float* __restrict__ b4,
            const float* __restrict__ pD, const float* __restrict__ pchi)
{
    extern __shared__ char smem[];
    const uint32_t smem_u = smem_to_u32(smem);
    const int tid  = threadIdx.x;
    const int wid  = tid >> 5;
    const int lane = tid & 31;
    const int r0   = lane >> 2;        // 0..7 : lower m-row of this lane
    const int v    = r0 & 3;           // fixed Taylor stream of this lane
    const int cpair = lane & 3;        // col-pair index

    // ---- stage split-bf16 W (k-major, swizzled) + constants ----
    {
        const float* src[3] = {W1, W2, W3};
        for (int L = 0; L < 3; ++L) {
            char* hiB = smem + L * 65536;
            char* loB = hiB + 32768;
            for (int idx = tid; idx < H * H; idx += NTHREADS) {
                int k = idx >> 7, n = idx & 127;
                float f = src[L][idx];
                __nv_bfloat16 bh = __float2bfloat16_rn(f);
                float hiF = __bfloat162float(bh);
                int o = k * 256 + ((((n >> 3) ^ (k & 7)) << 4)) + ((n & 7) << 1);
                *(__nv_bfloat16*)(hiB + o) = bh;
                *(__nv_bfloat16*)(loB + o) = __float2bfloat16_rn(f - hiF);
            }
        }
        float* sc = (float*)(smem + SM_CONST);
        for (int j = tid; j < H; j += NTHREADS) {
            sc[0 * 128 + j] = b1[j];
            sc[1 * 128 + j] = b2[j];
            sc[2 * 128 + j] = b3[j];
            sc[3 * 128 + j] = W0[j];
            sc[4 * 128 + j] = W0[H + j];
            sc[5 * 128 + j] = b0[j];
            sc[6 * 128 + j] = W4[j];
        }
    }
    __syncthreads();

    const float* sc    = (const float*)(smem + SM_CONST);
    const float* s_w0x = sc + 384;
    const float* s_w0t = sc + 512;
    const float* s_b0  = sc + 640;
    const float* s_w4  = sc + 768;
    const float b4v  = __ldg(&b4[0]);
    const float Dv   = __ldg(&pD[0]);
    const float chiv = __ldg(&pchi[0]);

    double local = 0.0;

    for (int base = (blockIdx.x * 8 + wid) * PTS_PER_WARP; base < NTOT;
         base += PASS_STRIDE) {

        // ---- classify 4 points (uniform across lanes) ----
        float px[4], pt[4]; int pty[4];
        #pragma unroll
        for (int q = 0; q < 4; ++q) {
            int pid = base + q;
            float x = 0.f, t = 0.f; int ty = 3;
            if (pid < NCOLP)                    { x = x_col[pid];               t = t_col[pid];              ty = 0; }
            else if (pid < NCOLP + NICP)        { int u_ = pid - NCOLP;         x = x_ic[u_];  t = t_ic[u_]; ty = 1; }
            else if (pid < NCOLP + NICP + NBCP) { int u_ = pid - NCOLP - NICP;  x = x_bcl[u_]; t = t_bc[u_]; ty = 2; }
            else if (pid < NTOT)                { int u_ = pid-NCOLP-NICP-NBCP; x = x_bcr[u_]; t = t_bc[u_]; ty = 2; }
            px[q] = x; pt[q] = t; pty[q] = ty;
        }
        const int   pa = r0 >> 2, pb = pa + 2;       // points of rows r0, r0+8
        const float xA = px[pa], tA = pt[pa];
        const float xB = px[pb], tB = pt[pb];

        // ---- layer 0: build A-frags directly in registers ----
        // val[half*4 + rr*2 + e]: register r = 2*half + rr holds (row, cols k0+8h+e)
        // which is exactly the PTX m16n8k16 A layout: a0=(g,c) a1=(g+8,c) a2=(g,c+8) a3=(g+8,c+8)
        unsigned ah[8][4], al[8][4];
        #pragma unroll
        for (int kt = 0; kt < 8; ++kt) {
            int k0 = 16 * kt + 2 * cpair;
            float val[8];
            #pragma unroll
            for (int half = 0; half < 2; ++half) {      // k0 / k0+8
                int kk = k0 + 8 * half;
                float2 wx = *(const float2*)&s_w0x[kk];
                float2 wt = *(const float2*)&s_w0t[kk];
                float2 bb = *(const float2*)&s_b0[kk];
                #pragma unroll
                for (int rr = 0; rr < 2; ++rr) {        // rows r0 / r0+8
                    float x = rr ? xB : xA, t = rr ? tB : tA;
                    #pragma unroll
                    for (int e = 0; e < 2; ++e) {       // col kk / kk+1
                        float wxe = e ? wx.y : wx.x;
                        float wte = e ? wt.y : wt.x;
                        float bbe = e ? bb.y : bb.x;
                        float z = fmaf(x, wxe, fmaf(t, wte, bbe));
                        float eb  = __expf(-z);
                        float s   = __fdividef(1.f, 1.f + eb);
                        float s1s = s * (1.f - s);
                        float f1  = fmaf(z, s1s, s);
                        float r;
                        if (v == 0)      r = z * s;
                        else if (v == 1) r = f1 * wxe;
                        else if (v == 2) r = f1 * wte;
                        else {
                            float f2 = s1s * fmaf(z, fmaf(-2.f, s, 1.f), 2.f);
                            r = f2 * wxe * wxe;
                        }
                        val[half * 4 + rr * 2 + e] = r;
                    }
                }
            }
            repack8(val, ah[kt], al[kt]);   // identity order
        }

        // ---- hidden layers 1,2 with repack; layer 3 with loss epilogue ----
        float C[16][4];
        #pragma unroll 1
        for (int L = 0; L < 2; ++L) {
            mma_layer(C, ah, al, smem_u + L * 65536, smem_u + L * 65536 + 32768, lane);
            const float* sbL = sc + L * 128;
            #pragma unroll
            for (int t = 0; t < 8; ++t) {
                int n0 = 16 * t + 2 * cpair;
                float z[8] = { C[2*t][0], C[2*t][1], C[2*t][2], C[2*t][3],
                               C[2*t+1][0], C[2*t+1][1], C[2*t+1][2], C[2*t+1][3] };
                float val[8];
                act8(z, v, lane, sbL, n0, val);
                repack8(val, ah[t], al[t]);
            }
        }
        mma_layer(C, ah, al, smem_u + 2 * 65536, smem_u + 2 * 65536 + 32768, lane);

        // ---- final activation + W4 dot ----
        float dA = 0.f, dB = 0.f;
        {
            const float* sb3 = sc + 2 * 128;
            #pragma unroll
            for (int t = 0; t < 8; ++t) {
                int n0 = 16 * t + 2 * cpair;
                float z[8] = { C[2*t][0], C[2*t][1], C[2*t][2], C[2*t][3],
                               C[2*t+1][0], C[2*t+1][1], C[2*t+1][2], C[2*t+1][3] };
                float val[8];
                act8(z, v, lane, sb3, n0, val);
                float2 wa = *(const float2*)&s_w4[n0];
                float2 wb = *(const float2*)&s_w4[n0 + 8];
                dA = fmaf(val[0], wa.x, dA); dA = fmaf(val[1], wa.y, dA);
                dA = fmaf(val[4], wb.x, dA); dA = fmaf(val[5], wb.y, dA);
                dB = fmaf(val[2], wa.x, dB); dB = fmaf(val[3], wa.y, dB);
                dB = fmaf(val[6], wb.x, dB); dB = fmaf(val[7], wb.y, dB);
            }
        }
        // reduce over the 4 col-lanes
        dA += __shfl_xor_sync(0xffffffffu, dA, 1);
        dA += __shfl_xor_sync(0xffffffffu, dA, 2);
        dB += __shfl_xor_sync(0xffffffffu, dB, 1);
        dB += __shfl_xor_sync(0xffffffffu, dB, 2);
        // gather the 4 streams of this lane-half's points
        const int gbase = lane & ~15;
        float uA[4], uB[4];
        #pragma unroll
        for (int vv = 0; vv < 4; ++vv) {
            uA[vv] = __shfl_sync(0xffffffffu, dA, gbase | (vv << 2));
            uB[vv] = __shfl_sync(0xffffffffu, dB, gbase | (vv << 2));
        }
        if ((lane & 15) == 0) {
            int myp[2] = { lane >> 4, (lane >> 4) + 2 };
            float* us[2] = { uA, uB };
            #pragma unroll
            for (int h = 0; h < 2; ++h) {
                int p = myp[h];
                float uu  = us[h][0] + b4v;
                float ux  = us[h][1];
                float ut  = us[h][2];
                float uxx = us[h][3];
                float x = px[p];
                float contrib = 0.f;
                int ty = pty[p];
                if (ty == 0) {
                    float a   = x - 0.7f;
                    float E   = __expf(-50.f * a * a);
                    float dS  = -100.f * a * E;
                    float dS2 = 100.f * E * fmaf(100.f * a, a, -1.f);
                    float res = ut - Dv * uxx + chiv * (ux * dS + uu * dS2);
                    contrib = res * res * (1.f / NCOLP);
                } else if (ty == 1) {
                    float d0  = x - 0.3f;
                    float icv = 0.1f + 0.05f * __expf(-100.f * d0 * d0);
                    float d   = uu - icv;
                    contrib = d * d * (1.f / NICP);
                } else if (ty == 2) {
                    contrib = ux * ux * (1.f / NBCP);
                }
                local += (double)contrib;
            }
        }
    }

    // ---- reduction ----
    #pragma unroll
    for (int off = 16; off; off >>= 1) {
        long long bits = __shfl_xor_sync(0xffffffffu, __double_as_longlong(local), off);
        local += __longlong_as_double(bits);
    }
    double* red = (double*)(smem + SM_RED);
    __syncthreads();
    if (lane == 0) red[wid] = local;
    __syncthreads();
    if (tid == 0) {
        double s = 0.0;
        #pragma unroll
        for (int w = 0; w < 8; ++w) s += red[w];
        atomicAdd(&g_acc, s);
    }
}

__global__ void k_zero() { g_acc = 0.0; }
__global__ void k_final(float* out) { out[0] = (float)g_acc; }

extern "C" void kernel_launch(void* const* d_in, const int* in_sizes, int n_in,
                              void* d_out, int out_size) {
    (void)in_sizes; (void)n_in; (void)out_size;
    cudaFuncSetAttribute(pinn_kernel,
                         cudaFuncAttributeMaxDynamicSharedMemorySize, SMEM_BYTES);
    k_zero<<<1, 1>>>();
    pinn_kernel<<<NBLOCKS, NTHREADS, SMEM_BYTES>>>(
        (const float*)d_in[0],  (const float*)d_in[1],  (const float*)d_in[2],
        (const float*)d_in[3],  (const float*)d_in[4],  (const float*)d_in[5],
        (const float*)d_in[6],  (const float*)d_in[7],  (const float*)d_in[8],
        (const float*)d_in[9],  (const float*)d_in[10], (const float*)d_in[11],
        (const float*)d_in[12], (const float*)d_in[13], (const float*)d_in[14],
        (const float*)d_in[15], (const float*)d_in[16], (const float*)d_in[17],
        (const float*)d_in[18]);
    k_final<<<1, 1>>>((float*)d_out);
}

// round 10
// speedup vs baseline: 2.0678x; 1.0341x over previous
#include <cuda_runtime.h>
#include <cuda_bf16.h>
#include <cstdint>

#define H 128
#define NCOLP 131072
#define NICP  2000
#define NBCP  2000
#define NTOT  (NCOLP + NICP + 2*NBCP)
#define NBLOCKS 148
#define NTHREADS 256
#define PTS_PER_WARP 4
#define PASS_STRIDE (NBLOCKS * 8 * PTS_PER_WARP)   // 4736 points per grid pass

// ---- smem byte offsets ----
// W blocks: for L in 0..2: Wh at L*65536, Wl at L*65536+32768 (each 32KB, [k][n] bf16,
// 256B rows, 16B-chunk XOR swizzle: chunk' = chunk ^ (k&7))
#define SM_W     0
#define SM_CONST 196608
// const floats: [0]=b1,[128]=b2,[256]=b3,[384]=w0x,[512]=w0t,[640]=b0,[768]=W4
#define SMEM_BYTES (SM_CONST + 3584)

__device__ double g_partial[NBLOCKS];
__device__ unsigned g_count = 0;

__device__ __forceinline__ uint32_t smem_to_u32(const void* p) {
    uint32_t a;
    asm("{ .reg .u64 t; cvta.to.shared.u64 t, %1; cvt.u32.u64 %0, t; }"
        : "=r"(a) : "l"(p));
    return a;
}

__device__ __forceinline__ void mma_bf16(float* c, const unsigned* a,
                                         unsigned b0, unsigned b1) {
    asm volatile("mma.sync.aligned.m16n8k16.row.col.f32.bf16.bf16.f32 "
        "{%0,%1,%2,%3}, {%4,%5,%6,%7}, {%8,%9}, {%0,%1,%2,%3};"
        : "+f"(c[0]), "+f"(c[1]), "+f"(c[2]), "+f"(c[3])
        : "r"(a[0]), "r"(a[1]), "r"(a[2]), "r"(a[3]), "r"(b0), "r"(b1));
}
__device__ __forceinline__ void ldsm4t(unsigned* r, uint32_t addr) {
    asm volatile("ldmatrix.sync.aligned.m8n8.x4.trans.shared.b16 {%0,%1,%2,%3}, [%4];"
        : "=r"(r[0]), "=r"(r[1]), "=r"(r[2]), "=r"(r[3]) : "r"(addr));
}

// split val pairs into hi (bf16-rn) + lo (bf16-rn of exact residual)
__device__ __forceinline__ void repack8(const float* val, unsigned* aht, unsigned* alt) {
    #pragma unroll
    for (int q = 0; q < 4; ++q) {
        float v0 = val[2*q], v1 = val[2*q + 1];
        unsigned hp;
        asm("cvt.rn.bf16x2.f32 %0, %1, %2;" : "=r"(hp) : "f"(v1), "f"(v0));
        float h0 = __uint_as_float(hp << 16);           // low half -> f32
        float h1 = __uint_as_float(hp & 0xFFFF0000u);   // high half -> f32
        float l0 = v0 - h0, l1 = v1 - h1;
        unsigned lp;
        asm("cvt.rn.bf16x2.f32 %0, %1, %2;" : "=r"(lp) : "f"(l1), "f"(l0));
        aht[q] = hp; alt[q] = lp;
    }
}

// one GEMM layer: C[16 tiles][4] = (Ah+Al)*(Wh+Wl), 3 products.
// kt-outer / np-inner; C-tile targets alternate so same-accumulator
// dependency distance is >=2 and the unrolled np loop exposes 16 chains.
__device__ __forceinline__ void mma_layer(float (&C)[16][4],
                                          const unsigned (&ah)[8][4],
                                          const unsigned (&al)[8][4],
                                          uint32_t whB, uint32_t wlB, int lane) {
    #pragma unroll
    for (int nt = 0; nt < 16; ++nt)
        #pragma unroll
        for (int q = 0; q < 4; ++q) C[nt][q] = 0.f;
    const int g = lane >> 3, lr = lane & 7;
    const int krow = ((g & 1) << 3) + lr;    // row within ktile
    const int ccg  = g >> 1;                 // which n8-chunk of the pair
    #pragma unroll
    for (int kt = 0; kt < 8; ++kt) {
        const int k = 16 * kt + krow;
        const uint32_t rowb = (uint32_t)(k * 256);
        const unsigned kx = (unsigned)(k & 7);
        #pragma unroll
        for (int np = 0; np < 8; ++np) {
            int cc = 2 * np + ccg;
            uint32_t off = rowb + (((unsigned)cc ^ kx) << 4);
            unsigned bh[4], bl[4];
            ldsm4t(bh, whB + off);
            ldsm4t(bl, wlB + off);
            mma_bf16(C[2*np],   ah[kt], bh[0], bh[1]);
            mma_bf16(C[2*np+1], ah[kt], bh[2], bh[3]);
            mma_bf16(C[2*np],   al[kt], bh[0], bh[1]);
            mma_bf16(C[2*np+1], al[kt], bh[2], bh[3]);
            mma_bf16(C[2*np],   ah[kt], bl[0], bl[1]);
            mma_bf16(C[2*np+1], ah[kt], bl[2], bl[3]);
        }
    }
}

// SiLU-Taylor activation on 8 C-elements of one tile-pair.
__device__ __forceinline__ void act8(float* z, int v, int lane,
                                     const float* sbL, int n0, float* val) {
    if (v == 0) {   // bias only enters the value stream
        float2 ba = *(const float2*)&sbL[n0];
        float2 bb = *(const float2*)&sbL[n0 + 8];
        z[0] += ba.x; z[1] += ba.y; z[2] += ba.x; z[3] += ba.y;
        z[4] += bb.x; z[5] += bb.y; z[6] += bb.x; z[7] += bb.y;
    }
    const int zl = (lane & ~15) | (lane & 3);   // v=0 lane of this (point, col)
    #pragma unroll
    for (int i = 0; i < 8; ++i) {
        float zm = z[i];
        float z0 = __shfl_sync(0xffffffffu, zm, zl);
        float zx = __shfl_sync(0xffffffffu, zm, zl + 4);
        float e   = __expf(-z0);
        float s   = __fdividef(1.f, 1.f + e);
        float s1s = s * (1.f - s);
        float f1  = fmaf(z0, s1s, s);
        float f2  = s1s * fmaf(z0, fmaf(-2.f, s, 1.f), 2.f);
        float av  = z0 * s;                       // value stream
        float dv  = f1 * zm;                      // d/dx, d/dt streams
        float xv  = fmaf(f2 * zx, zx, f1 * zm);   // d2/dx2 stream
        val[i] = (v == 0) ? av : ((v == 3) ? xv : dv);
    }
}

extern "C" __global__ void __launch_bounds__(NTHREADS, 1)
pinn_kernel(const float* __restrict__ x_col, const float* __restrict__ t_col,
            const float* __restrict__ x_ic,  const float* __restrict__ t_ic,
            const float* __restrict__ x_bcl, const float* __restrict__ x_bcr,
            const float* __restrict__ t_bc,
            const float* __restrict__ W0, const float* __restrict__ b0,
            const float* __restrict__ W1, const float* __restrict__ b1,
            const float* __restrict__ W2, const float* __restrict__ b2,
            const float* __restrict__ W3, const float* __restrict__ b3,
            const float* __restrict__ W4, const float* __restrict__ b4,
            const float* __restrict__ pD, const float* __restrict__ pchi,
            float* __restrict__ out)
{
    extern __shared__ char smem[];
    const uint32_t smem_u = smem_to_u32(smem);
    const int tid  = threadIdx.x;
    const int wid  = tid >> 5;
    const int lane = tid & 31;
    const int r0   = lane >> 2;        // 0..7 : lower m-row of this lane
    const int v    = r0 & 3;           // fixed Taylor stream of this lane
    const int cpair = lane & 3;        // col-pair index

    __shared__ double s_red[8];
    __shared__ int s_last;

    // ---- stage split-bf16 W (k-major, swizzled) + constants ----
    {
        const float* src[3] = {W1, W2, W3};
        for (int L = 0; L < 3; ++L) {
            char* hiB = smem + L * 65536;
            char* loB = hiB + 32768;
            for (int idx = tid; idx < H * H; idx += NTHREADS) {
                int k = idx >> 7, n = idx & 127;
                float f = src[L][idx];
                __nv_bfloat16 bh = __float2bfloat16_rn(f);
                float hiF = __bfloat162float(bh);
                int o = k * 256 + ((((n >> 3) ^ (k & 7)) << 4)) + ((n & 7) << 1);
                *(__nv_bfloat16*)(hiB + o) = bh;
                *(__nv_bfloat16*)(loB + o) = __float2bfloat16_rn(f - hiF);
            }
        }
        float* sc = (float*)(smem + SM_CONST);
        for (int j = tid; j < H; j += NTHREADS) {
            sc[0 * 128 + j] = b1[j];
            sc[1 * 128 + j] = b2[j];
            sc[2 * 128 + j] = b3[j];
            sc[3 * 128 + j] = W0[j];
            sc[4 * 128 + j] = W0[H + j];
            sc[5 * 128 + j] = b0[j];
            sc[6 * 128 + j] = W4[j];
        }
    }
    __syncthreads();

    const float* sc    = (const float*)(smem + SM_CONST);
    const float* s_w0x = sc + 384;
    const float* s_w0t = sc + 512;
    const float* s_b0  = sc + 640;
    const float* s_w4  = sc + 768;
    const float b4v  = __ldg(&b4[0]);
    const float Dv   = __ldg(&pD[0]);
    const float chiv = __ldg(&pchi[0]);

    double local = 0.0;

    for (int base = (blockIdx.x * 8 + wid) * PTS_PER_WARP; base < NTOT;
         base += PASS_STRIDE) {

        // ---- classify 4 points (uniform across lanes) ----
        float px[4], pt[4]; int pty[4];
        #pragma unroll
        for (int q = 0; q < 4; ++q) {
            int pid = base + q;
            float x = 0.f, t = 0.f; int ty = 3;
            if (pid < NCOLP)                    { x = x_col[pid];               t = t_col[pid];              ty = 0; }
            else if (pid < NCOLP + NICP)        { int u_ = pid - NCOLP;         x = x_ic[u_];  t = t_ic[u_]; ty = 1; }
            else if (pid < NCOLP + NICP + NBCP) { int u_ = pid - NCOLP - NICP;  x = x_bcl[u_]; t = t_bc[u_]; ty = 2; }
            else if (pid < NTOT)                { int u_ = pid-NCOLP-NICP-NBCP; x = x_bcr[u_]; t = t_bc[u_]; ty = 2; }
            px[q] = x; pt[q] = t; pty[q] = ty;
        }
        const int   pa = r0 >> 2, pb = pa + 2;       // points of rows r0, r0+8
        const float xA = px[pa], tA = pt[pa];
        const float xB = px[pb], tB = pt[pb];

        // ---- layer 0: build A-frags directly in registers (identity order) ----
        unsigned ah[8][4], al[8][4];
        #pragma unroll
        for (int kt = 0; kt < 8; ++kt) {
            int k0 = 16 * kt + 2 * cpair;
            float val[8];
            #pragma unroll
            for (int half = 0; half < 2; ++half) {      // k0 / k0+8
                int kk = k0 + 8 * half;
                float2 wx = *(const float2*)&s_w0x[kk];
                float2 wt = *(const float2*)&s_w0t[kk];
                float2 bb = *(const float2*)&s_b0[kk];
                #pragma unroll
                for (int rr = 0; rr < 2; ++rr) {        // rows r0 / r0+8
                    float x = rr ? xB : xA, t = rr ? tB : tA;
                    #pragma unroll
                    for (int e = 0; e < 2; ++e) {       // col kk / kk+1
                        float wxe = e ? wx.y : wx.x;
                        float wte = e ? wt.y : wt.x;
                        float bbe = e ? bb.y : bb.x;
                        float z = fmaf(x, wxe, fmaf(t, wte, bbe));
                        float eb  = __expf(-z);
                        float s   = __fdividef(1.f, 1.f + eb);
                        float s1s = s * (1.f - s);
                        float f1  = fmaf(z, s1s, s);
                        float r;
                        if (v == 0)      r = z * s;
                        else if (v == 1) r = f1 * wxe;
                        else if (v == 2) r = f1 * wte;
                        else {
                            float f2 = s1s * fmaf(z, fmaf(-2.f, s, 1.f), 2.f);
                            r = f2 * wxe * wxe;
                        }
                        val[half * 4 + rr * 2 + e] = r;
                    }
                }
            }
            repack8(val, ah[kt], al[kt]);
        }

        // ---- hidden layers 1,2 with repack; layer 3 with loss epilogue ----
        float C[16][4];
        #pragma unroll 1
        for (int L = 0; L < 2; ++L) {
            mma_layer(C, ah, al, smem_u + L * 65536, smem_u + L * 65536 + 32768, lane);
            const float* sbL = sc + L * 128;
            #pragma unroll
            for (int t = 0; t < 8; ++t) {
                int n0 = 16 * t + 2 * cpair;
                float z[8] = { C[2*t][0], C[2*t][1], C[2*t][2], C[2*t][3],
                               C[2*t+1][0], C[2*t+1][1], C[2*t+1][2], C[2*t+1][3] };
                float val[8];
                act8(z, v, lane, sbL, n0, val);
                repack8(val, ah[t], al[t]);
            }
        }
        mma_layer(C, ah, al, smem_u + 2 * 65536, smem_u + 2 * 65536 + 32768, lane);

        // ---- final activation + W4 dot ----
        float dA = 0.f, dB = 0.f;
        {
            const float* sb3 = sc + 2 * 128;
            #pragma unroll
            for (int t = 0; t < 8; ++t) {
                int n0 = 16 * t + 2 * cpair;
                float z[8] = { C[2*t][0], C[2*t][1], C[2*t][2], C[2*t][3],
                               C[2*t+1][0], C[2*t+1][1], C[2*t+1][2], C[2*t+1][3] };
                float val[8];
                act8(z, v, lane, sb3, n0, val);
                float2 wa = *(const float2*)&s_w4[n0];
                float2 wb = *(const float2*)&s_w4[n0 + 8];
                dA = fmaf(val[0], wa.x, dA); dA = fmaf(val[1], wa.y, dA);
                dA = fmaf(val[4], wb.x, dA); dA = fmaf(val[5], wb.y, dA);
                dB = fmaf(val[2], wa.x, dB); dB = fmaf(val[3], wa.y, dB);
                dB = fmaf(val[6], wb.x, dB); dB = fmaf(val[7], wb.y, dB);
            }
        }
        // reduce over the 4 col-lanes
        dA += __shfl_xor_sync(0xffffffffu, dA, 1);
        dA += __shfl_xor_sync(0xffffffffu, dA, 2);
        dB += __shfl_xor_sync(0xffffffffu, dB, 1);
        dB += __shfl_xor_sync(0xffffffffu, dB, 2);
        // gather the 4 streams of this lane-half's points
        const int gbase = lane & ~15;
        float uA[4], uB[4];
        #pragma unroll
        for (int vv = 0; vv < 4; ++vv) {
            uA[vv] = __shfl_sync(0xffffffffu, dA, gbase | (vv << 2));
            uB[vv] = __shfl_sync(0xffffffffu, dB, gbase | (vv << 2));
        }
        if ((lane & 15) == 0) {
            int myp[2] = { lane >> 4, (lane >> 4) + 2 };
            float* us[2] = { uA, uB };
            #pragma unroll
            for (int h = 0; h < 2; ++h) {
                int p = myp[h];
                float uu  = us[h][0] + b4v;
                float ux  = us[h][1];
                float ut  = us[h][2];
                float uxx = us[h][3];
                float x = px[p];
                float contrib = 0.f;
                int ty = pty[p];
                if (ty == 0) {
                    float a   = x - 0.7f;
                    float E   = __expf(-50.f * a * a);
                    float dS  = -100.f * a * E;
                    float dS2 = 100.f * E * fmaf(100.f * a, a, -1.f);
                    float res = ut - Dv * uxx + chiv * (ux * dS + uu * dS2);
                    contrib = res * res * (1.f / NCOLP);
                } else if (ty == 1) {
                    float d0  = x - 0.3f;
                    float icv = 0.1f + 0.05f * __expf(-100.f * d0 * d0);
                    float d   = uu - icv;
                    contrib = d * d * (1.f / NICP);
                } else if (ty == 2) {
                    contrib = ux * ux * (1.f / NBCP);
                }
                local += (double)contrib;
            }
        }
    }

    // ---- block sum -> g_partial; last block reduces and writes out ----
    #pragma unroll
    for (int off = 16; off; off >>= 1) {
        long long bits = __shfl_xor_sync(0xffffffffu, __double_as_longlong(local), off);
        local += __longlong_as_double(bits);
    }
    if (lane == 0) s_red[wid] = local;
    __syncthreads();
    if (tid == 0) {
        double s = 0.0;
        #pragma unroll
        for (int w = 0; w < 8; ++w) s += s_red[w];
        g_partial[blockIdx.x] = s;
        __threadfence();
        unsigned old = atomicAdd(&g_count, 1u);
        s_last = (old == NBLOCKS - 1) ? 1 : 0;
        if (s_last) g_count = 0;        // self-reset for next graph replay
    }
    __syncthreads();
    if (s_last) {
        // block-parallel final reduction of 148 partials
        double ps = 0.0;
        for (int b = tid; b < NBLOCKS; b += NTHREADS) ps += g_partial[b];
        #pragma unroll
        for (int off = 16; off; off >>= 1) {
            long long bits = __shfl_xor_sync(0xffffffffu, __double_as_longlong(ps), off);
            ps += __longlong_as_double(bits);
        }
        if (lane == 0) s_red[wid] = ps;
        __syncthreads();
        if (tid == 0) {
            double s = 0.0;
            #pragma unroll
            for (int w = 0; w < 8; ++w) s += s_red[w];
            out[0] = (float)s;
        }
    }
}

extern "C" void kernel_launch(void* const* d_in, const int* in_sizes, int n_in,
                              void* d_out, int out_size) {
    (void)in_sizes; (void)n_in; (void)out_size;
    cudaFuncSetAttribute(pinn_kernel,
                         cudaFuncAttributeMaxDynamicSharedMemorySize, SMEM_BYTES);
    pinn_kernel<<<NBLOCKS, NTHREADS, SMEM_BYTES>>>(
        (const float*)d_in[0],  (const float*)d_in[1],  (const float*)d_in[2],
        (const float*)d_in[3],  (const float*)d_in[4],  (const float*)d_in[5],
        (const float*)d_in[6],  (const float*)d_in[7],  (const float*)d_in[8],
        (const float*)d_in[9],  (const float*)d_in[10], (const float*)d_in[11],
        (const float*)d_in[12], (const float*)d_in[13], (const float*)d_in[14],
        (const float*)d_in[15], (const float*)d_in[16], (const float*)d_in[17],
        (const float*)d_in[18], (float*)d_out);
}